// round 16
// baseline (speedup 1.0000x reference)
#include <cuda_runtime.h>
#include <cuda_fp16.h>
#include <cstdint>

// ---------------------------------------------------------------------------
// GCN: h1 = relu((ÂX)W1 + b1); h2 = relu((Âh1)W2 + b2); mean pool; MLP head.
// CSR gather (fp16, fp32 accum) -> fp16 agg; cp.async double-buffered fp16
// HMMA GEMMs; fused W-prep / f2h; multi-graph pooled MLP (smem-tiled Wf1).
// ---------------------------------------------------------------------------

#define MAX_NODES 100000
#define MAX_EDGES 1700000
#define HID 256
#define NGRAPH 2048
#define SCAN_CHUNK 512
#define MAX_SCAN_BLOCKS ((MAX_NODES + SCAN_CHUNK - 1) / SCAN_CHUNK)
#define GPB 8    // graphs per pool/MLP block

__device__ __half g_aggH[(size_t)MAX_NODES * HID];
__device__ __half g_h1h[(size_t)MAX_NODES * HID];
__device__ __half g_h2h[(size_t)MAX_NODES * HID];
__device__ __half g_xh[(size_t)MAX_NODES * 128];
__device__ float  g_dinv[MAX_NODES];
__device__ __half g_Wh[256 * 256];                   // W^T fp16 [N][K]
__device__ int    g_cntI[MAX_NODES];
__device__ int    g_rowptr[MAX_NODES + 1];
__device__ int    g_cursor[MAX_NODES];
__device__ uint2  g_edge[MAX_EDGES];                 // {src, norm}
__device__ int    g_partial[MAX_SCAN_BLOCKS];

// ========================= helpers =========================
#define LDMX4(R, ADDR)                                                          \
    asm volatile("ldmatrix.sync.aligned.m8n8.x4.shared.b16 {%0,%1,%2,%3}, [%4];" \
                 : "=r"((R)[0]), "=r"((R)[1]), "=r"((R)[2]), "=r"((R)[3])        \
                 : "r"(ADDR))

#define MMAF16(D, A, B0, B1)                                                    \
    asm volatile("mma.sync.aligned.m16n8k16.row.col.f32.f16.f16.f32 "            \
                 "{%0,%1,%2,%3}, {%4,%5,%6,%7}, {%8,%9}, {%0,%1,%2,%3};"         \
                 : "+f"((D)[0]), "+f"((D)[1]), "+f"((D)[2]), "+f"((D)[3])        \
                 : "r"((A)[0]), "r"((A)[1]), "r"((A)[2]), "r"((A)[3]),           \
                   "r"(B0), "r"(B1))

#define CP_ASYNC16(dst, src) \
    asm volatile("cp.async.cg.shared.global [%0], [%1], 16;" :: "r"(dst), "l"(src))
#define CP_COMMIT()  asm volatile("cp.async.commit_group;" ::: "memory")
#define CP_WAIT1()   asm volatile("cp.async.wait_group 1;" ::: "memory")
#define CP_WAIT0()   asm volatile("cp.async.wait_group 0;" ::: "memory")

// ===================== CSR construction =====================
__global__ void k_count_f2h(const int* __restrict__ dst, int* __restrict__ cnt, int nE,
                            int nbCount, const float* __restrict__ X,
                            __half* __restrict__ Xh, long t4) {
    if ((int)blockIdx.x < nbCount) {
        int i = blockIdx.x * 256 + threadIdx.x;
        if (i < nE) atomicAdd(&cnt[dst[i]], 1);
    } else {
        long i = (long)(blockIdx.x - nbCount) * 256 + threadIdx.x;
        if (i < t4) {
            float4 v = ((const float4*)X)[i];
            __half2 h0 = __floats2half2_rn(v.x, v.y);
            __half2 h1 = __floats2half2_rn(v.z, v.w);
            ((uint2*)Xh)[i] = make_uint2(*(uint32_t*)&h0, *(uint32_t*)&h1);
        }
    }
}
__global__ void k_scan_p1(const int* __restrict__ cnt, int* __restrict__ partial, int n) {
    __shared__ int s[256];
    int b = blockIdx.x, t = threadIdx.x;
    int base = b * SCAN_CHUNK;
    int i0 = base + t, i1 = base + 256 + t;
    int v = 0;
    if (i0 < n) v += cnt[i0];
    if (i1 < n) v += cnt[i1];
    s[t] = v;
    __syncthreads();
    #pragma unroll
    for (int off = 128; off > 0; off >>= 1) {
        if (t < off) s[t] += s[t + off];
        __syncthreads();
    }
    if (t == 0) partial[b] = s[0];
}
__global__ void k_scan_p2(int* __restrict__ partial, int nb) {
    __shared__ int s[256];
    int t = threadIdx.x;
    int v = (t < nb) ? partial[t] : 0;
    s[t] = v;
    __syncthreads();
    #pragma unroll
    for (int off = 1; off < 256; off <<= 1) {
        int u = (t >= off) ? s[t - off] : 0;
        __syncthreads();
        s[t] += u;
        __syncthreads();
    }
    if (t < nb) partial[t] = s[t] - v;
}
__global__ void k_scan_p3(const int* __restrict__ cnt, const int* __restrict__ partial,
                          int* __restrict__ rowptr, int* __restrict__ cursor,
                          float* __restrict__ dinv, int n) {
    __shared__ int s[256];
    int b = blockIdx.x, t = threadIdx.x;
    int base = b * SCAN_CHUNK;
    int i0 = base + 2 * t, i1 = i0 + 1;
    int c0 = (i0 < n) ? cnt[i0] : 0;
    int c1 = (i1 < n) ? cnt[i1] : 0;
    int pairSum = c0 + c1;
    s[t] = pairSum;
    __syncthreads();
    #pragma unroll
    for (int off = 1; off < 256; off <<= 1) {
        int u = (t >= off) ? s[t - off] : 0;
        __syncthreads();
        s[t] += u;
        __syncthreads();
    }
    int pre = s[t] - pairSum + partial[b];
    if (i0 < n) {
        rowptr[i0] = pre; cursor[i0] = pre;
        dinv[i0] = rsqrtf((float)(c0 + 1));
        if (i0 == n - 1) rowptr[n] = pre + c0;
    }
    if (i1 < n) {
        rowptr[i1] = pre + c0; cursor[i1] = pre + c0;
        dinv[i1] = rsqrtf((float)(c1 + 1));
        if (i1 == n - 1) rowptr[n] = pre + c0 + c1;
    }
}
__global__ void k_fill(const int* __restrict__ src, const int* __restrict__ dst,
                       const float* __restrict__ dinv, int* __restrict__ cursor,
                       uint2* __restrict__ edges, int nE) {
    int i = blockIdx.x * blockDim.x + threadIdx.x;
    if (i >= nE) return;
    int s = src[i], d = dst[i];
    int pos = atomicAdd(&cursor[d], 1);
    float nm = dinv[s] * dinv[d];
    edges[pos] = make_uint2((unsigned)s, __float_as_uint(nm));
}

// ===================== CSR gather (fp16 in, fp16 out) ==================
__device__ __forceinline__ void acc4h(float4& a, uint2 u, float nm) {
    float2 p0 = __half22float2(*(__half2*)&u.x);
    float2 p1 = __half22float2(*(__half2*)&u.y);
    a.x += nm * p0.x; a.y += nm * p0.y; a.z += nm * p1.x; a.w += nm * p1.y;
}
__device__ __forceinline__ void acc8h(float4& a0, float4& a1, uint4 u, float nm) {
    float2 p0 = __half22float2(*(__half2*)&u.x);
    float2 p1 = __half22float2(*(__half2*)&u.y);
    float2 p2 = __half22float2(*(__half2*)&u.z);
    float2 p3 = __half22float2(*(__half2*)&u.w);
    a0.x += nm * p0.x; a0.y += nm * p0.y; a0.z += nm * p1.x; a0.w += nm * p1.y;
    a1.x += nm * p2.x; a1.y += nm * p2.y; a1.z += nm * p3.x; a1.w += nm * p3.y;
}
__device__ __forceinline__ uint2 pack4h(float4 a) {
    __half2 h0 = __floats2half2_rn(a.x, a.y);
    __half2 h1 = __floats2half2_rn(a.z, a.w);
    return make_uint2(*(uint32_t*)&h0, *(uint32_t*)&h1);
}
__device__ __forceinline__ void prep_w_tail(const float* __restrict__ W,
                                            __half* __restrict__ Wh, int K,
                                            int blockOff) {
    int idx = ((int)blockIdx.x - blockOff) * 256 + threadIdx.x;
    if (idx >= K * 256) return;
    int n = idx / K, k = idx % K;
    Wh[idx] = __float2half_rn(W[(size_t)k * 256 + n]);
}

// layer 1: 128 cols; tail blocks do W1 prep
__global__ __launch_bounds__(256)
void k_gather128h(const __half* __restrict__ Xh,
                  const int* __restrict__ rowptr, const uint2* __restrict__ edges,
                  const float* __restrict__ dinv, __half* __restrict__ Agg, int n,
                  int gatherBlocks, const float* __restrict__ W, __half* __restrict__ Wh) {
    if ((int)blockIdx.x >= gatherBlocks) {
        prep_w_tail(W, Wh, 128, gatherBlocks);
        return;
    }
    int node = (blockIdx.x * 256 + threadIdx.x) >> 5;
    if (node >= n) return;
    int lane = threadIdx.x & 31;
    float di = dinv[node];
    float s2 = di * di;
    const uint2* Xv = (const uint2*)Xh;
    float4 a = make_float4(0.f, 0.f, 0.f, 0.f);
    acc4h(a, Xv[(size_t)node * 32 + lane], s2);
    int e = rowptr[node], e1 = rowptr[node + 1];
    for (; e + 4 <= e1; e += 4) {
        uint2 E0 = edges[e],     E1 = edges[e + 1];
        uint2 E2 = edges[e + 2], E3 = edges[e + 3];
        uint2 u0 = Xv[(size_t)E0.x * 32 + lane];
        uint2 u1 = Xv[(size_t)E1.x * 32 + lane];
        uint2 u2 = Xv[(size_t)E2.x * 32 + lane];
        uint2 u3 = Xv[(size_t)E3.x * 32 + lane];
        acc4h(a, u0, __uint_as_float(E0.y));
        acc4h(a, u1, __uint_as_float(E1.y));
        acc4h(a, u2, __uint_as_float(E2.y));
        acc4h(a, u3, __uint_as_float(E3.y));
    }
    for (; e < e1; ++e) {
        uint2 E = edges[e];
        acc4h(a, Xv[(size_t)E.x * 32 + lane], __uint_as_float(E.y));
    }
    __stcs(&((uint2*)Agg)[(size_t)node * 32 + lane], pack4h(a));
}

// layer 2: 256 cols; tail blocks do W2 prep
__global__ __launch_bounds__(256)
void k_gather256h(const __half* __restrict__ H,
                  const int* __restrict__ rowptr, const uint2* __restrict__ edges,
                  const float* __restrict__ dinv, __half* __restrict__ Agg, int n,
                  int gatherBlocks, const float* __restrict__ W, __half* __restrict__ Wh) {
    if ((int)blockIdx.x >= gatherBlocks) {
        prep_w_tail(W, Wh, 256, gatherBlocks);
        return;
    }
    int node = (blockIdx.x * 256 + threadIdx.x) >> 5;
    if (node >= n) return;
    int lane = threadIdx.x & 31;
    float di = dinv[node];
    float s2 = di * di;
    const uint4* Hv = (const uint4*)H;
    float4 a0 = make_float4(0.f, 0.f, 0.f, 0.f);
    float4 a1 = make_float4(0.f, 0.f, 0.f, 0.f);
    acc8h(a0, a1, Hv[(size_t)node * 32 + lane], s2);
    int e = rowptr[node], e1 = rowptr[node + 1];
    for (; e + 4 <= e1; e += 4) {
        uint2 E0 = edges[e],     E1 = edges[e + 1];
        uint2 E2 = edges[e + 2], E3 = edges[e + 3];
        uint4 u0 = Hv[(size_t)E0.x * 32 + lane];
        uint4 u1 = Hv[(size_t)E1.x * 32 + lane];
        uint4 u2 = Hv[(size_t)E2.x * 32 + lane];
        uint4 u3 = Hv[(size_t)E3.x * 32 + lane];
        acc8h(a0, a1, u0, __uint_as_float(E0.y));
        acc8h(a0, a1, u1, __uint_as_float(E1.y));
        acc8h(a0, a1, u2, __uint_as_float(E2.y));
        acc8h(a0, a1, u3, __uint_as_float(E3.y));
    }
    for (; e < e1; ++e) {
        uint2 E = edges[e];
        acc8h(a0, a1, Hv[(size_t)E.x * 32 + lane], __uint_as_float(E.y));
    }
    uint2 p0 = pack4h(a0), p1 = pack4h(a1);
    __stcs(&((uint4*)Agg)[(size_t)node * 32 + lane], make_uint4(p0.x, p0.y, p1.x, p1.y));
}

// ===================== tensor-core GEMM (M x K) @ (K x 256) =================
#define BM 128
#define BN 128
#define BK 32
#define LDS_PAD 40

__global__ __launch_bounds__(256, 3)
void k_gemm_mma(const __half* __restrict__ A, const __half* __restrict__ B,
                const float* __restrict__ bias, __half* __restrict__ C,
                int M, int K) {
    __shared__ __align__(16) __half sA[2][BM * LDS_PAD];
    __shared__ __align__(16) __half sB[2][BN * LDS_PAD];

    const int tid = threadIdx.x;
    const int wid = tid >> 5, lane = tid & 31;
    const int warpM = wid & 3;
    const int warpN = wid >> 2;
    const int rowBase = blockIdx.y * BM;
    const int colBase = blockIdx.x * BN;

    float acc[2][8][4];
    #pragma unroll
    for (int i = 0; i < 2; i++)
        #pragma unroll
        for (int j = 0; j < 8; j++)
            #pragma unroll
            for (int q = 0; q < 4; q++) acc[i][j][q] = 0.f;

    const int aRow = warpM * 32 + (lane & 15);
    const int aK   = (lane >> 4) * 8;
    const int bRowBase = warpN * 64 + (lane & 7) + ((lane >> 4) << 3);
    const int bK   = ((lane >> 3) & 1) * 8;

    uint32_t sA_b = (uint32_t)__cvta_generic_to_shared(sA);
    uint32_t sB_b = (uint32_t)__cvta_generic_to_shared(sB);
    const uint32_t STAGE = BM * LDS_PAD * 2;

    const int lr  = tid >> 2;
    const int lc8 = (tid & 3) * 8;

    auto issueLoads = [&](int k0, int st) {
        #pragma unroll
        for (int it = 0; it < 2; ++it) {
            int r = lr + it * 64;
            int gr = rowBase + r; if (gr >= M) gr = M - 1;
            const __half* srcA = A + (size_t)gr * K + k0 + lc8;
            CP_ASYNC16(sA_b + st * STAGE + (uint32_t)(r * LDS_PAD + lc8) * 2, srcA);
            const __half* srcB = B + (size_t)(colBase + r) * K + k0 + lc8;
            CP_ASYNC16(sB_b + st * STAGE + (uint32_t)(r * LDS_PAD + lc8) * 2, srcB);
        }
        CP_COMMIT();
    };

    const int nCh = K >> 5;
    issueLoads(0, 0);
    for (int c = 0; c < nCh; ++c) {
        int st = c & 1;
        if (c + 1 < nCh) {
            issueLoads((c + 1) << 5, st ^ 1);
            CP_WAIT1();
        } else {
            CP_WAIT0();
        }
        __syncthreads();

        uint32_t baseA = sA_b + st * STAGE;
        uint32_t baseB = sB_b + st * STAGE;
        #pragma unroll
        for (int kk = 0; kk < BK; kk += 16) {
            uint32_t aR[2][4];
            #pragma unroll
            for (int mi = 0; mi < 2; ++mi) {
                uint32_t o = (uint32_t)((aRow + mi * 16) * LDS_PAD + kk + aK) * 2;
                LDMX4(aR[mi], baseA + o);
            }
            #pragma unroll
            for (int nj = 0; nj < 4; ++nj) {
                uint32_t bR[4];
                uint32_t o = (uint32_t)((bRowBase + nj * 16) * LDS_PAD + kk + bK) * 2;
                LDMX4(bR, baseB + o);
                #pragma unroll
                for (int mi = 0; mi < 2; ++mi) {
                    MMAF16(acc[mi][nj * 2 + 0], aR[mi], bR[0], bR[1]);
                    MMAF16(acc[mi][nj * 2 + 1], aR[mi], bR[2], bR[3]);
                }
            }
        }
        __syncthreads();
    }

    const int erow = rowBase + warpM * 32 + (lane >> 2);
    const int ecol = colBase + warpN * 64 + (lane & 3) * 2;
    #pragma unroll
    for (int mi = 0; mi < 2; ++mi) {
        int r0 = erow + mi * 16;
        #pragma unroll
        for (int nj = 0; nj < 8; ++nj) {
            int c = ecol + nj * 8;
            float b0 = bias[c], b1 = bias[c + 1];
            float v00 = fmaxf(acc[mi][nj][0] + b0, 0.f);
            float v01 = fmaxf(acc[mi][nj][1] + b1, 0.f);
            float v10 = fmaxf(acc[mi][nj][2] + b0, 0.f);
            float v11 = fmaxf(acc[mi][nj][3] + b1, 0.f);
            if (r0 < M)     *(__half2*)(C + (size_t)r0 * 256 + c)       = __floats2half2_rn(v00, v01);
            if (r0 + 8 < M) *(__half2*)(C + (size_t)(r0 + 8) * 256 + c) = __floats2half2_rn(v10, v11);
        }
    }
}

// ===== pooling + MLP: GPB graphs per block, Wf1 tiled through smem =====
__global__ __launch_bounds__(256)
void k_pool_mlp(const __half* __restrict__ H, const int* __restrict__ batch,
                const float* __restrict__ Wf1, const float* __restrict__ bf1,
                const float* __restrict__ Wf2, const float* __restrict__ bf2,
                float* __restrict__ out, int n) {
    __shared__ float pooled[GPB][HID];     // 8 KB
    __shared__ float wchunk[64][128];      // 32 KB
    __shared__ float hid[GPB][128];        // 4 KB
    int t = threadIdx.x;
    int warp = t >> 5, lane = t & 31;
    int gBase = blockIdx.x * GPB;

    // Phase A: warp w pools graph gBase+w (same accumulation order as before)
    {
        int g = gBase + warp;
        int lo = 0, hi = n;
        while (lo < hi) { int mid = (lo + hi) >> 1; if (batch[mid] < g) lo = mid + 1; else hi = mid; }
        int start = lo;
        hi = n;
        while (lo < hi) { int mid = (lo + hi) >> 1; if (batch[mid] < g + 1) lo = mid + 1; else hi = mid; }
        int end = lo;
        float4 a0 = make_float4(0.f, 0.f, 0.f, 0.f);
        float4 a1 = make_float4(0.f, 0.f, 0.f, 0.f);
        const uint4* Hv = (const uint4*)H;
        for (int i = start; i < end; ++i)
            acc8h(a0, a1, Hv[(size_t)i * 32 + lane], 1.0f);
        float inv = (end > start) ? 1.0f / (float)(end - start) : 0.f;
        int c = 8 * lane;
        pooled[warp][c + 0] = a0.x * inv; pooled[warp][c + 1] = a0.y * inv;
        pooled[warp][c + 2] = a0.z * inv; pooled[warp][c + 3] = a0.w * inv;
        pooled[warp][c + 4] = a1.x * inv; pooled[warp][c + 5] = a1.y * inv;
        pooled[warp][c + 6] = a1.z * inv; pooled[warp][c + 7] = a1.w * inv;
    }
    __syncthreads();

    // Phase B: hid[g][j] = relu(sum_k pooled[g][k]*Wf1[k][j] + bf1[j]) * Wf2[j]
    int j = t & 127;
    int gh = t >> 7;       // 0 or 1 -> graphs gh*4 .. gh*4+3
    float acc[4];
    float bj = bf1[j];
    #pragma unroll
    for (int q = 0; q < 4; ++q) acc[q] = bj;
    for (int k0 = 0; k0 < HID; k0 += 64) {
        for (int i = t; i < 64 * 128; i += 256)
            wchunk[i >> 7][i & 127] = Wf1[(size_t)(k0 + (i >> 7)) * 128 + (i & 127)];
        __syncthreads();
        #pragma unroll 8
        for (int kk = 0; kk < 64; ++kk) {
            float w = wchunk[kk][j];
            #pragma unroll
            for (int q = 0; q < 4; ++q)
                acc[q] += pooled[gh * 4 + q][k0 + kk] * w;
        }
        __syncthreads();
    }
    float w2 = Wf2[j];
    #pragma unroll
    for (int q = 0; q < 4; ++q)
        hid[gh * 4 + q][j] = fmaxf(acc[q], 0.f) * w2;
    __syncthreads();

    // Phase C: warp w reduces graph w's 128 values
    {
        float s = hid[warp][lane] + hid[warp][lane + 32] +
                  hid[warp][lane + 64] + hid[warp][lane + 96];
        #pragma unroll
        for (int o = 16; o > 0; o >>= 1)
            s += __shfl_xor_sync(0xffffffffu, s, o);
        if (lane == 0) out[gBase + warp] = s + bf2[0];
    }
}

// ---------------------------------------------------------------------------
extern "C" void kernel_launch(void* const* d_in, const int* in_sizes, int n_in,
                              void* d_out, int out_size) {
    const float* x   = (const float*)d_in[0];
    const int*   ei  = (const int*)d_in[1];
    const int*   bat = (const int*)d_in[2];
    const float* W1  = (const float*)d_in[3];
    const float* b1  = (const float*)d_in[4];
    const float* W2  = (const float*)d_in[5];
    const float* b2  = (const float*)d_in[6];
    const float* Wf1 = (const float*)d_in[7];
    const float* bf1 = (const float*)d_in[8];
    const float* Wf2 = (const float*)d_in[9];
    const float* bf2 = (const float*)d_in[10];
    float* out = (float*)d_out;

    int n  = in_sizes[0] / 128;
    int nE = in_sizes[1] / 2;
    const int* src = ei;
    const int* dst = ei + nE;

    float *dinv;
    __half *aggH, *h1h, *h2h, *xh, *Wh;
    int *cntI, *rowptr, *cursor, *partial;
    uint2 *edges;
    cudaGetSymbolAddress((void**)&aggH, g_aggH);
    cudaGetSymbolAddress((void**)&h1h,  g_h1h);
    cudaGetSymbolAddress((void**)&h2h,  g_h2h);
    cudaGetSymbolAddress((void**)&xh,   g_xh);
    cudaGetSymbolAddress((void**)&dinv, g_dinv);
    cudaGetSymbolAddress((void**)&Wh,   g_Wh);
    cudaGetSymbolAddress((void**)&cntI, g_cntI);
    cudaGetSymbolAddress((void**)&rowptr, g_rowptr);
    cudaGetSymbolAddress((void**)&cursor, g_cursor);
    cudaGetSymbolAddress((void**)&edges, g_edge);
    cudaGetSymbolAddress((void**)&partial, g_partial);

    // --- CSR build + x->fp16 ---
    int nb = (n + SCAN_CHUNK - 1) / SCAN_CHUNK;
    cudaMemsetAsync(cntI, 0, (size_t)n * sizeof(int));
    {
        int nbCount = (nE + 255) / 256;
        long t4 = (long)n * 32;
        int nbF2h = (int)((t4 + 255) / 256);
        k_count_f2h<<<nbCount + nbF2h, 256>>>(dst, cntI, nE, nbCount, x, xh, t4);
    }
    k_scan_p1<<<nb, 256>>>(cntI, partial, n);
    k_scan_p2<<<1, 256>>>(partial, nb);
    k_scan_p3<<<nb, 256>>>(cntI, partial, rowptr, cursor, dinv, n);
    k_fill<<<(nE + 255) / 256, 256>>>(src, dst, dinv, cursor, edges, nE);

    dim3 gemmGrid(2, (n + BM - 1) / BM);
    int gatherBlocks = (int)(((long)n * 32 + 255) / 256);

    // --- layer 1 (gather + W1 prep fused) ---
    k_gather128h<<<gatherBlocks + 128, 256>>>(xh, rowptr, edges, dinv, aggH, n,
                                              gatherBlocks, W1, Wh);
    k_gemm_mma<<<gemmGrid, 256>>>(aggH, Wh, b1, h1h, n, 128);

    // --- layer 2 (gather + W2 prep fused) ---
    k_gather256h<<<gatherBlocks + 256, 256>>>(h1h, rowptr, edges, dinv, aggH, n,
                                              gatherBlocks, W2, Wh);
    k_gemm_mma<<<gemmGrid, 256>>>(aggH, Wh, b2, h2h, n, 256);

    // --- pooling + MLP head (8 graphs per block) ---
    k_pool_mlp<<<NGRAPH / GPB, 256>>>(h2h, bat, Wf1, bf1, Wf2, bf2, out, n);
}

// round 17
// speedup vs baseline: 1.1410x; 1.1410x over previous
#include <cuda_runtime.h>
#include <cuda_fp16.h>
#include <cstdint>

// ---------------------------------------------------------------------------
// GCN: h1 = relu((ÂX)W1 + b1); h2 = relu((Âh1)W2 + b2); mean pool; MLP head.
// CSR gather (fp16, fp32 accum) -> fp16 agg; 3-stage cp.async fp16 HMMA
// GEMMs; fused W-prep / f2h / pool+MLP.  (round-11 base + 3-stage GEMM)
// ---------------------------------------------------------------------------

#define MAX_NODES 100000
#define MAX_EDGES 1700000
#define HID 256
#define NGRAPH 2048
#define SCAN_CHUNK 512
#define MAX_SCAN_BLOCKS ((MAX_NODES + SCAN_CHUNK - 1) / SCAN_CHUNK)

__device__ __half g_aggH[(size_t)MAX_NODES * HID];
__device__ __half g_h1h[(size_t)MAX_NODES * HID];
__device__ __half g_h2h[(size_t)MAX_NODES * HID];
__device__ __half g_xh[(size_t)MAX_NODES * 128];
__device__ float  g_dinv[MAX_NODES];
__device__ __half g_Wh[256 * 256];                   // W^T fp16 [N][K]
__device__ int    g_cntI[MAX_NODES];
__device__ int    g_rowptr[MAX_NODES + 1];
__device__ int    g_cursor[MAX_NODES];
__device__ uint2  g_edge[MAX_EDGES];                 // {src, norm}
__device__ int    g_partial[MAX_SCAN_BLOCKS];

// ========================= helpers =========================
#define LDMX4(R, ADDR)                                                          \
    asm volatile("ldmatrix.sync.aligned.m8n8.x4.shared.b16 {%0,%1,%2,%3}, [%4];" \
                 : "=r"((R)[0]), "=r"((R)[1]), "=r"((R)[2]), "=r"((R)[3])        \
                 : "r"(ADDR))

#define MMAF16(D, A, B0, B1)                                                    \
    asm volatile("mma.sync.aligned.m16n8k16.row.col.f32.f16.f16.f32 "            \
                 "{%0,%1,%2,%3}, {%4,%5,%6,%7}, {%8,%9}, {%0,%1,%2,%3};"         \
                 : "+f"((D)[0]), "+f"((D)[1]), "+f"((D)[2]), "+f"((D)[3])        \
                 : "r"((A)[0]), "r"((A)[1]), "r"((A)[2]), "r"((A)[3]),           \
                   "r"(B0), "r"(B1))

#define CP_ASYNC16(dst, src) \
    asm volatile("cp.async.cg.shared.global [%0], [%1], 16;" :: "r"(dst), "l"(src))
#define CP_COMMIT()  asm volatile("cp.async.commit_group;" ::: "memory")
#define CP_WAIT2()   asm volatile("cp.async.wait_group 2;" ::: "memory")
#define CP_WAIT1()   asm volatile("cp.async.wait_group 1;" ::: "memory")
#define CP_WAIT0()   asm volatile("cp.async.wait_group 0;" ::: "memory")

// ===================== CSR construction =====================
__global__ void k_count_f2h(const int* __restrict__ dst, int* __restrict__ cnt, int nE,
                            int nbCount, const float* __restrict__ X,
                            __half* __restrict__ Xh, long t4) {
    if ((int)blockIdx.x < nbCount) {
        int i = blockIdx.x * 256 + threadIdx.x;
        if (i < nE) atomicAdd(&cnt[dst[i]], 1);
    } else {
        long i = (long)(blockIdx.x - nbCount) * 256 + threadIdx.x;
        if (i < t4) {
            float4 v = ((const float4*)X)[i];
            __half2 h0 = __floats2half2_rn(v.x, v.y);
            __half2 h1 = __floats2half2_rn(v.z, v.w);
            ((uint2*)Xh)[i] = make_uint2(*(uint32_t*)&h0, *(uint32_t*)&h1);
        }
    }
}
__global__ void k_scan_p1(const int* __restrict__ cnt, int* __restrict__ partial, int n) {
    __shared__ int s[256];
    int b = blockIdx.x, t = threadIdx.x;
    int base = b * SCAN_CHUNK;
    int i0 = base + t, i1 = base + 256 + t;
    int v = 0;
    if (i0 < n) v += cnt[i0];
    if (i1 < n) v += cnt[i1];
    s[t] = v;
    __syncthreads();
    #pragma unroll
    for (int off = 128; off > 0; off >>= 1) {
        if (t < off) s[t] += s[t + off];
        __syncthreads();
    }
    if (t == 0) partial[b] = s[0];
}
__global__ void k_scan_p2(int* __restrict__ partial, int nb) {
    __shared__ int s[256];
    int t = threadIdx.x;
    int v = (t < nb) ? partial[t] : 0;
    s[t] = v;
    __syncthreads();
    #pragma unroll
    for (int off = 1; off < 256; off <<= 1) {
        int u = (t >= off) ? s[t - off] : 0;
        __syncthreads();
        s[t] += u;
        __syncthreads();
    }
    if (t < nb) partial[t] = s[t] - v;
}
__global__ void k_scan_p3(const int* __restrict__ cnt, const int* __restrict__ partial,
                          int* __restrict__ rowptr, int* __restrict__ cursor,
                          float* __restrict__ dinv, int n) {
    __shared__ int s[256];
    int b = blockIdx.x, t = threadIdx.x;
    int base = b * SCAN_CHUNK;
    int i0 = base + 2 * t, i1 = i0 + 1;
    int c0 = (i0 < n) ? cnt[i0] : 0;
    int c1 = (i1 < n) ? cnt[i1] : 0;
    int pairSum = c0 + c1;
    s[t] = pairSum;
    __syncthreads();
    #pragma unroll
    for (int off = 1; off < 256; off <<= 1) {
        int u = (t >= off) ? s[t - off] : 0;
        __syncthreads();
        s[t] += u;
        __syncthreads();
    }
    int pre = s[t] - pairSum + partial[b];
    if (i0 < n) {
        rowptr[i0] = pre; cursor[i0] = pre;
        dinv[i0] = rsqrtf((float)(c0 + 1));
        if (i0 == n - 1) rowptr[n] = pre + c0;
    }
    if (i1 < n) {
        rowptr[i1] = pre + c0; cursor[i1] = pre + c0;
        dinv[i1] = rsqrtf((float)(c1 + 1));
        if (i1 == n - 1) rowptr[n] = pre + c0 + c1;
    }
}
__global__ void k_fill(const int* __restrict__ src, const int* __restrict__ dst,
                       const float* __restrict__ dinv, int* __restrict__ cursor,
                       uint2* __restrict__ edges, int nE) {
    int i = blockIdx.x * blockDim.x + threadIdx.x;
    if (i >= nE) return;
    int s = src[i], d = dst[i];
    int pos = atomicAdd(&cursor[d], 1);
    float nm = dinv[s] * dinv[d];
    edges[pos] = make_uint2((unsigned)s, __float_as_uint(nm));
}

// ===================== CSR gather (fp16 in, fp16 out) ==================
__device__ __forceinline__ void acc4h(float4& a, uint2 u, float nm) {
    float2 p0 = __half22float2(*(__half2*)&u.x);
    float2 p1 = __half22float2(*(__half2*)&u.y);
    a.x += nm * p0.x; a.y += nm * p0.y; a.z += nm * p1.x; a.w += nm * p1.y;
}
__device__ __forceinline__ void acc8h(float4& a0, float4& a1, uint4 u, float nm) {
    float2 p0 = __half22float2(*(__half2*)&u.x);
    float2 p1 = __half22float2(*(__half2*)&u.y);
    float2 p2 = __half22float2(*(__half2*)&u.z);
    float2 p3 = __half22float2(*(__half2*)&u.w);
    a0.x += nm * p0.x; a0.y += nm * p0.y; a0.z += nm * p1.x; a0.w += nm * p1.y;
    a1.x += nm * p2.x; a1.y += nm * p2.y; a1.z += nm * p3.x; a1.w += nm * p3.y;
}
__device__ __forceinline__ uint2 pack4h(float4 a) {
    __half2 h0 = __floats2half2_rn(a.x, a.y);
    __half2 h1 = __floats2half2_rn(a.z, a.w);
    return make_uint2(*(uint32_t*)&h0, *(uint32_t*)&h1);
}
__device__ __forceinline__ void prep_w_tail(const float* __restrict__ W,
                                            __half* __restrict__ Wh, int K,
                                            int blockOff) {
    int idx = ((int)blockIdx.x - blockOff) * 256 + threadIdx.x;
    if (idx >= K * 256) return;
    int n = idx / K, k = idx % K;
    Wh[idx] = __float2half_rn(W[(size_t)k * 256 + n]);
}

// layer 1: 128 cols; tail blocks do W1 prep
__global__ __launch_bounds__(256)
void k_gather128h(const __half* __restrict__ Xh,
                  const int* __restrict__ rowptr, const uint2* __restrict__ edges,
                  const float* __restrict__ dinv, __half* __restrict__ Agg, int n,
                  int gatherBlocks, const float* __restrict__ W, __half* __restrict__ Wh) {
    if ((int)blockIdx.x >= gatherBlocks) {
        prep_w_tail(W, Wh, 128, gatherBlocks);
        return;
    }
    int node = (blockIdx.x * 256 + threadIdx.x) >> 5;
    if (node >= n) return;
    int lane = threadIdx.x & 31;
    float di = dinv[node];
    float s2 = di * di;
    const uint2* Xv = (const uint2*)Xh;
    float4 a = make_float4(0.f, 0.f, 0.f, 0.f);
    acc4h(a, Xv[(size_t)node * 32 + lane], s2);
    int e = rowptr[node], e1 = rowptr[node + 1];
    for (; e + 4 <= e1; e += 4) {
        uint2 E0 = edges[e],     E1 = edges[e + 1];
        uint2 E2 = edges[e + 2], E3 = edges[e + 3];
        uint2 u0 = Xv[(size_t)E0.x * 32 + lane];
        uint2 u1 = Xv[(size_t)E1.x * 32 + lane];
        uint2 u2 = Xv[(size_t)E2.x * 32 + lane];
        uint2 u3 = Xv[(size_t)E3.x * 32 + lane];
        acc4h(a, u0, __uint_as_float(E0.y));
        acc4h(a, u1, __uint_as_float(E1.y));
        acc4h(a, u2, __uint_as_float(E2.y));
        acc4h(a, u3, __uint_as_float(E3.y));
    }
    for (; e < e1; ++e) {
        uint2 E = edges[e];
        acc4h(a, Xv[(size_t)E.x * 32 + lane], __uint_as_float(E.y));
    }
    __stcs(&((uint2*)Agg)[(size_t)node * 32 + lane], pack4h(a));
}

// layer 2: 256 cols; tail blocks do W2 prep
__global__ __launch_bounds__(256)
void k_gather256h(const __half* __restrict__ H,
                  const int* __restrict__ rowptr, const uint2* __restrict__ edges,
                  const float* __restrict__ dinv, __half* __restrict__ Agg, int n,
                  int gatherBlocks, const float* __restrict__ W, __half* __restrict__ Wh) {
    if ((int)blockIdx.x >= gatherBlocks) {
        prep_w_tail(W, Wh, 256, gatherBlocks);
        return;
    }
    int node = (blockIdx.x * 256 + threadIdx.x) >> 5;
    if (node >= n) return;
    int lane = threadIdx.x & 31;
    float di = dinv[node];
    float s2 = di * di;
    const uint4* Hv = (const uint4*)H;
    float4 a0 = make_float4(0.f, 0.f, 0.f, 0.f);
    float4 a1 = make_float4(0.f, 0.f, 0.f, 0.f);
    acc8h(a0, a1, Hv[(size_t)node * 32 + lane], s2);
    int e = rowptr[node], e1 = rowptr[node + 1];
    for (; e + 4 <= e1; e += 4) {
        uint2 E0 = edges[e],     E1 = edges[e + 1];
        uint2 E2 = edges[e + 2], E3 = edges[e + 3];
        uint4 u0 = Hv[(size_t)E0.x * 32 + lane];
        uint4 u1 = Hv[(size_t)E1.x * 32 + lane];
        uint4 u2 = Hv[(size_t)E2.x * 32 + lane];
        uint4 u3 = Hv[(size_t)E3.x * 32 + lane];
        acc8h(a0, a1, u0, __uint_as_float(E0.y));
        acc8h(a0, a1, u1, __uint_as_float(E1.y));
        acc8h(a0, a1, u2, __uint_as_float(E2.y));
        acc8h(a0, a1, u3, __uint_as_float(E3.y));
    }
    for (; e < e1; ++e) {
        uint2 E = edges[e];
        acc8h(a0, a1, Hv[(size_t)E.x * 32 + lane], __uint_as_float(E.y));
    }
    uint2 p0 = pack4h(a0), p1 = pack4h(a1);
    __stcs(&((uint4*)Agg)[(size_t)node * 32 + lane], make_uint4(p0.x, p0.y, p1.x, p1.y));
}

// ===================== tensor-core GEMM (M x K) @ (K x 256) =================
// 3-stage cp.async pipeline; dynamic smem.
#define BM 128
#define BN 128
#define BK 32
#define LDS_PAD 40
#define STAGE_BYTES (BM * LDS_PAD * 2)            /* per tensor per stage: 10240 B */
#define GEMM_SMEM (3 * 2 * STAGE_BYTES)           /* 61440 B */

__global__ __launch_bounds__(256, 2)
void k_gemm_mma(const __half* __restrict__ A, const __half* __restrict__ B,
                const float* __restrict__ bias, __half* __restrict__ C,
                int M, int K) {
    extern __shared__ __align__(16) char smem[];
    uint32_t smem_b = (uint32_t)__cvta_generic_to_shared(smem);

    const int tid = threadIdx.x;
    const int wid = tid >> 5, lane = tid & 31;
    const int warpM = wid & 3;
    const int warpN = wid >> 2;
    const int rowBase = blockIdx.y * BM;
    const int colBase = blockIdx.x * BN;

    float acc[2][8][4];
    #pragma unroll
    for (int i = 0; i < 2; i++)
        #pragma unroll
        for (int j = 0; j < 8; j++)
            #pragma unroll
            for (int q = 0; q < 4; q++) acc[i][j][q] = 0.f;

    const int aRow = warpM * 32 + (lane & 15);
    const int aK   = (lane >> 4) * 8;
    const int bRowBase = warpN * 64 + (lane & 7) + ((lane >> 4) << 3);
    const int bK   = ((lane >> 3) & 1) * 8;

    const int lr  = tid >> 2;          // 0..63
    const int lc8 = (tid & 3) * 8;

    auto issueLoads = [&](int k0, int st) {
        uint32_t baseA = smem_b + (uint32_t)st * (2 * STAGE_BYTES);
        uint32_t baseB = baseA + STAGE_BYTES;
        #pragma unroll
        for (int it = 0; it < 2; ++it) {
            int r = lr + it * 64;
            int gr = rowBase + r; if (gr >= M) gr = M - 1;
            const __half* srcA = A + (size_t)gr * K + k0 + lc8;
            CP_ASYNC16(baseA + (uint32_t)(r * LDS_PAD + lc8) * 2, srcA);
            const __half* srcB = B + (size_t)(colBase + r) * K + k0 + lc8;
            CP_ASYNC16(baseB + (uint32_t)(r * LDS_PAD + lc8) * 2, srcB);
        }
        CP_COMMIT();
    };

    const int nCh = K >> 5;
    issueLoads(0, 0);
    if (nCh > 1) issueLoads(32, 1);
    for (int c = 0; c < nCh; ++c) {
        if (c + 2 < nCh) {
            issueLoads((c + 2) << 5, (c + 2) % 3);
            CP_WAIT2();
        } else if (c + 1 < nCh) {
            CP_WAIT1();
        } else {
            CP_WAIT0();
        }
        __syncthreads();

        int st = c % 3;
        uint32_t baseA = smem_b + (uint32_t)st * (2 * STAGE_BYTES);
        uint32_t baseB = baseA + STAGE_BYTES;
        #pragma unroll
        for (int kk = 0; kk < BK; kk += 16) {
            uint32_t aR[2][4];
            #pragma unroll
            for (int mi = 0; mi < 2; ++mi) {
                uint32_t o = (uint32_t)((aRow + mi * 16) * LDS_PAD + kk + aK) * 2;
                LDMX4(aR[mi], baseA + o);
            }
            #pragma unroll
            for (int nj = 0; nj < 4; ++nj) {
                uint32_t bR[4];
                uint32_t o = (uint32_t)((bRowBase + nj * 16) * LDS_PAD + kk + bK) * 2;
                LDMX4(bR, baseB + o);
                #pragma unroll
                for (int mi = 0; mi < 2; ++mi) {
                    MMAF16(acc[mi][nj * 2 + 0], aR[mi], bR[0], bR[1]);
                    MMAF16(acc[mi][nj * 2 + 1], aR[mi], bR[2], bR[3]);
                }
            }
        }
        __syncthreads();
    }

    const int erow = rowBase + warpM * 32 + (lane >> 2);
    const int ecol = colBase + warpN * 64 + (lane & 3) * 2;
    #pragma unroll
    for (int mi = 0; mi < 2; ++mi) {
        int r0 = erow + mi * 16;
        #pragma unroll
        for (int nj = 0; nj < 8; ++nj) {
            int c = ecol + nj * 8;
            float b0 = bias[c], b1 = bias[c + 1];
            float v00 = fmaxf(acc[mi][nj][0] + b0, 0.f);
            float v01 = fmaxf(acc[mi][nj][1] + b1, 0.f);
            float v10 = fmaxf(acc[mi][nj][2] + b0, 0.f);
            float v11 = fmaxf(acc[mi][nj][3] + b1, 0.f);
            if (r0 < M)     *(__half2*)(C + (size_t)r0 * 256 + c)       = __floats2half2_rn(v00, v01);
            if (r0 + 8 < M) *(__half2*)(C + (size_t)(r0 + 8) * 256 + c) = __floats2half2_rn(v10, v11);
        }
    }
}

// ============ fused pooling + MLP head: one block per graph ============
__global__ __launch_bounds__(128)
void k_pool_mlp(const __half* __restrict__ H, const int* __restrict__ batch,
                const float* __restrict__ Wf1, const float* __restrict__ bf1,
                const float* __restrict__ Wf2, const float* __restrict__ bf2,
                float* __restrict__ out, int n) {
    int g = blockIdx.x;
    int t = threadIdx.x;
    __shared__ float p[HID];
    __shared__ float red[128];

    int lo = 0, hi = n;
    while (lo < hi) { int mid = (lo + hi) >> 1; if (batch[mid] < g) lo = mid + 1; else hi = mid; }
    int start = lo;
    hi = n;
    while (lo < hi) { int mid = (lo + hi) >> 1; if (batch[mid] < g + 1) lo = mid + 1; else hi = mid; }
    int end = lo;

    float2 a = make_float2(0.f, 0.f);
    const uint32_t* Hu = (const uint32_t*)H;
    for (int i = start; i < end; ++i) {
        uint32_t u = Hu[(size_t)i * 128 + t];
        float2 v = __half22float2(*(__half2*)&u);
        a.x += v.x; a.y += v.y;
    }
    float inv = (end > start) ? 1.0f / (float)(end - start) : 0.f;
    p[2 * t]     = a.x * inv;
    p[2 * t + 1] = a.y * inv;
    __syncthreads();

    float acc = bf1[t];
    #pragma unroll 8
    for (int k = 0; k < HID; k++) acc += p[k] * Wf1[k * 128 + t];
    red[t] = fmaxf(acc, 0.f) * Wf2[t];
    __syncthreads();
    for (int s = 64; s > 0; s >>= 1) {
        if (t < s) red[t] += red[t + s];
        __syncthreads();
    }
    if (t == 0) out[g] = red[0] + bf2[0];
}

// ---------------------------------------------------------------------------
extern "C" void kernel_launch(void* const* d_in, const int* in_sizes, int n_in,
                              void* d_out, int out_size) {
    const float* x   = (const float*)d_in[0];
    const int*   ei  = (const int*)d_in[1];
    const int*   bat = (const int*)d_in[2];
    const float* W1  = (const float*)d_in[3];
    const float* b1  = (const float*)d_in[4];
    const float* W2  = (const float*)d_in[5];
    const float* b2  = (const float*)d_in[6];
    const float* Wf1 = (const float*)d_in[7];
    const float* bf1 = (const float*)d_in[8];
    const float* Wf2 = (const float*)d_in[9];
    const float* bf2 = (const float*)d_in[10];
    float* out = (float*)d_out;

    int n  = in_sizes[0] / 128;
    int nE = in_sizes[1] / 2;
    const int* src = ei;
    const int* dst = ei + nE;

    float *dinv;
    __half *aggH, *h1h, *h2h, *xh, *Wh;
    int *cntI, *rowptr, *cursor, *partial;
    uint2 *edges;
    cudaGetSymbolAddress((void**)&aggH, g_aggH);
    cudaGetSymbolAddress((void**)&h1h,  g_h1h);
    cudaGetSymbolAddress((void**)&h2h,  g_h2h);
    cudaGetSymbolAddress((void**)&xh,   g_xh);
    cudaGetSymbolAddress((void**)&dinv, g_dinv);
    cudaGetSymbolAddress((void**)&Wh,   g_Wh);
    cudaGetSymbolAddress((void**)&cntI, g_cntI);
    cudaGetSymbolAddress((void**)&rowptr, g_rowptr);
    cudaGetSymbolAddress((void**)&cursor, g_cursor);
    cudaGetSymbolAddress((void**)&edges, g_edge);
    cudaGetSymbolAddress((void**)&partial, g_partial);

    cudaFuncSetAttribute(k_gemm_mma, cudaFuncAttributeMaxDynamicSharedMemorySize,
                         GEMM_SMEM);

    // --- CSR build + x->fp16 ---
    int nb = (n + SCAN_CHUNK - 1) / SCAN_CHUNK;
    cudaMemsetAsync(cntI, 0, (size_t)n * sizeof(int));
    {
        int nbCount = (nE + 255) / 256;
        long t4 = (long)n * 32;
        int nbF2h = (int)((t4 + 255) / 256);
        k_count_f2h<<<nbCount + nbF2h, 256>>>(dst, cntI, nE, nbCount, x, xh, t4);
    }
    k_scan_p1<<<nb, 256>>>(cntI, partial, n);
    k_scan_p2<<<1, 256>>>(partial, nb);
    k_scan_p3<<<nb, 256>>>(cntI, partial, rowptr, cursor, dinv, n);
    k_fill<<<(nE + 255) / 256, 256>>>(src, dst, dinv, cursor, edges, nE);

    dim3 gemmGrid(2, (n + BM - 1) / BM);
    int gatherBlocks = (int)(((long)n * 32 + 255) / 256);

    // --- layer 1 (gather + W1 prep fused) ---
    k_gather128h<<<gatherBlocks + 128, 256>>>(xh, rowptr, edges, dinv, aggH, n,
                                              gatherBlocks, W1, Wh);
    k_gemm_mma<<<gemmGrid, 256, GEMM_SMEM>>>(aggH, Wh, b1, h1h, n, 128);

    // --- layer 2 (gather + W2 prep fused) ---
    k_gather256h<<<gatherBlocks + 256, 256>>>(h1h, rowptr, edges, dinv, aggH, n,
                                              gatherBlocks, W2, Wh);
    k_gemm_mma<<<gemmGrid, 256, GEMM_SMEM>>>(aggH, Wh, b2, h2h, n, 256);

    // --- fused pooling + MLP head ---
    k_pool_mlp<<<NGRAPH, 128>>>(h2h, bat, Wf1, bf1, Wf2, bf2, out, n);
}